// round 16
// baseline (speedup 1.0000x reference)
#include <cuda_runtime.h>
#include <cuda_fp16.h>
#include <math.h>

#define N_RAYS (4*128*128)
#define WARPS_PER_BLOCK 8

// corner-complete u32 entries: Q(b, xp, yp, zp) bytes =
//   { q(x,y,z), q(x,y,z+1), q(x,y+1,z), q(x,y+1,z+1) },  q = round(255*v)
// xp = x+1 (x in [-1,129]), yp = y+1 (y in [-1,128]), zp = z+4 (z in [-4,131])
#define PZ 136
#define PY 130
#define PX 131
#define SX (PY*PZ)             // 17680
#define PBATCH (PX*SX)         // 2316080
#define ROFF (SX + PZ + 4)     // 17820

__device__ float4   g_ray[N_RAYS * 2];
__device__ unsigned g_Q[4 * PBATCH];       // 37 MB

// role partition of the fused prep kernel
#define NBLK_PACK   256                    // 4*128*8*16 threads
#define NBLK_Y0     32                     // 4*128*16 threads
#define NROWS_B     (4 * (3 * PY + 128))   // 2072 full zero rows
#define NSINGLE_B   (4 * 128 * 129)        // 66048 zp=132 singles
#define NBLK_BORDER ((NROWS_B + NSINGLE_B + 255) / 256)   // 267
#define NBLK_SETUP  (N_RAYS / 256)         // 256
#define NBLK_PREP   (NBLK_PACK + NBLK_Y0 + NBLK_BORDER + NBLK_SETUP)

__device__ __forceinline__ unsigned q8(float v) {
    return __float2uint_rn(v * 255.0f);
}

// load 9 consecutive z values of one volume row, quantized+packed: C0=q0..q3, C1=q4..q7, c8
__device__ __forceinline__ void load_row9(
    const float* rowz, bool valid, bool has9,
    unsigned& C0, unsigned& C1, unsigned& c8)
{
    float4 a0 = make_float4(0.f,0.f,0.f,0.f), a1 = a0;
    float nx = 0.0f;
    if (valid) {
        a0 = __ldg((const float4*)rowz);
        a1 = __ldg((const float4*)(rowz + 4));
        if (has9) nx = __ldg(rowz + 8);
    }
    C0 = q8(a0.x) | (q8(a0.y) << 8) | (q8(a0.z) << 16) | (q8(a0.w) << 24);
    C1 = q8(a1.x) | (q8(a1.y) << 8) | (q8(a1.z) << 16) | (q8(a1.w) << 24);
    c8 = q8(nx);
}

// ---------------- fused prep ----------------
__global__ void __launch_bounds__(256) drr_prep_kernel(
    const float* __restrict__ vol,
    const float* __restrict__ params)
{
    const int blk = blockIdx.x;

    if (blk < NBLK_PACK) {
        // ---- pack: rolling y, entries yp in [1,128], 8 z per thread ----
        const int tid = blk * 256 + threadIdx.x;   // 65536
        const int zq = tid & 15;
        const int yg = (tid >> 4) & 7;
        const int x  = (tid >> 7) & 127;
        const int b  = tid >> 14;
        const int z0 = zq * 8;
        const bool has9 = (zq < 15);

        const float* rbase = vol + ((size_t)(b * 128 + x) * 128 + yg * 16) * 128 + z0;

        unsigned P0, P1, p8;
        load_row9(rbase, true, has9, P0, P1, p8);   // row y = 16yg

        size_t w = (size_t)b * PBATCH + (size_t)(x + 1) * SX
                 + (size_t)(yg * 16 + 1) * PZ + (z0 + 4);

        #pragma unroll
        for (int i = 1; i <= 16; i++) {
            unsigned C0, C1, c8;
            load_row9(rbase + (size_t)i * 128, (yg * 16 + i) < 128, has9, C0, C1, c8);

            unsigned e0 = __byte_perm(P0, C0, 0x5410);
            unsigned e1 = __byte_perm(P0, C0, 0x6521);
            unsigned e2 = __byte_perm(P0, C0, 0x7632);
            unsigned t  = __byte_perm(P0, P1, 0x0043);
            unsigned u  = __byte_perm(C0, C1, 0x0043);
            unsigned e3 = __byte_perm(t, u, 0x5410);
            unsigned e4 = __byte_perm(P1, C1, 0x5410);
            unsigned e5 = __byte_perm(P1, C1, 0x6521);
            unsigned e6 = __byte_perm(P1, C1, 0x7632);
            unsigned t2 = __byte_perm(P1, p8, 0x0043);
            unsigned u2 = __byte_perm(C1, c8, 0x0043);
            unsigned e7 = __byte_perm(t2, u2, 0x5410);

            *reinterpret_cast<uint4*>(&g_Q[w])     = make_uint4(e0, e1, e2, e3);
            *reinterpret_cast<uint4*>(&g_Q[w + 4]) = make_uint4(e4, e5, e6, e7);

            if (zq == 0)   // entry z = -1 (zp = 3): {0, q(y,0), 0, q(y+1,0)}
                g_Q[w - 1] = ((P0 & 0xFFu) << 8) | ((C0 & 0xFFu) << 24);

            P0 = C0; P1 = C1; p8 = c8;
            w += PZ;
        }
        return;
    }

    if (blk < NBLK_PACK + NBLK_Y0) {
        // ---- yp = 0 plane (y = -1): bytes {0, 0, q(0,z), q(0,z+1)} ----
        const int tid = (blk - NBLK_PACK) * 256 + threadIdx.x;   // 8192
        const int zq = tid & 15;
        const int x  = (tid >> 4) & 127;
        const int b  = tid >> 11;
        const int z0 = zq * 8;
        const bool has9 = (zq < 15);

        const float* rbase = vol + ((size_t)(b * 128 + x) * 128) * 128 + z0;   // row y=0
        unsigned C0, C1, c8;
        load_row9(rbase, true, has9, C0, C1, c8);

        unsigned e0 = __byte_perm(C0, 0, 0x1044);
        unsigned e1 = __byte_perm(C0, 0, 0x2144);
        unsigned e2 = __byte_perm(C0, 0, 0x3244);
        unsigned u  = __byte_perm(C0, C1, 0x0043);
        unsigned e3 = __byte_perm(u, 0, 0x1044);
        unsigned e4 = __byte_perm(C1, 0, 0x1044);
        unsigned e5 = __byte_perm(C1, 0, 0x2144);
        unsigned e6 = __byte_perm(C1, 0, 0x3244);
        unsigned u2 = __byte_perm(C1, c8, 0x0043);
        unsigned e7 = __byte_perm(u2, 0, 0x1044);

        size_t w = (size_t)b * PBATCH + (size_t)(x + 1) * SX + (z0 + 4);
        *reinterpret_cast<uint4*>(&g_Q[w])     = make_uint4(e0, e1, e2, e3);
        *reinterpret_cast<uint4*>(&g_Q[w + 4]) = make_uint4(e4, e5, e6, e7);

        if (zq == 0)   // entry (y=-1, z=-1): {0,0,0,q(0,0)}
            g_Q[w - 1] = (C0 & 0xFFu) << 24;
        return;
    }

    if (blk < NBLK_PACK + NBLK_Y0 + NBLK_BORDER) {
        // ---- borders: full zero rows + zp=132 singles ----
        const int t = (blk - NBLK_PACK - NBLK_Y0) * 256 + threadIdx.x;
        if (t < NROWS_B) {
            const int b = t / (3 * PY + 128);
            int r = t % (3 * PY + 128);
            int xp, yp;
            if (r < 3 * PY) {
                const int pl = r / PY;
                xp = (pl == 0) ? 0 : (pl == 1 ? 129 : 130);
                yp = r % PY;
            } else {
                xp = 1 + (r - 3 * PY);
                yp = 129;
            }
            size_t base = (size_t)b * PBATCH + (size_t)xp * SX + (size_t)yp * PZ;
            uint4 z4 = make_uint4(0u, 0u, 0u, 0u);
            #pragma unroll
            for (int i = 0; i < PZ / 4; i++)
                *reinterpret_cast<uint4*>(&g_Q[base + i * 4]) = z4;
            return;
        }
        const int s = t - NROWS_B;
        if (s >= NSINGLE_B) return;
        const int yp = s % 129;
        const int xq = (s / 129) & 127;
        const int b  = s / (129 * 128);
        g_Q[(size_t)b * PBATCH + (size_t)(xq + 1) * SX + (size_t)yp * PZ + 132] = 0u;
        return;
    }

    // ---- setup: per-ray geometry ----
    {
        const int ray = (blk - NBLK_PACK - NBLK_Y0 - NBLK_BORDER) * 256 + threadIdx.x;
        const int iv = ray & 127;
        const int iu = (ray >> 7) & 127;
        const int b  = ray >> 14;

        const float* p = params + b * 6;
        float sx, cx, sy, cy, szn, czn;
        __sincosf(p[0], &sx, &cx);
        __sincosf(p[1], &sy, &cy);
        __sincosf(p[2], &szn, &czn);

        float T00 = cy*czn,  T01 = cx*szn + sx*sy*czn,  T02 = sx*szn - cx*sy*czn;
        float T10 = -cy*szn, T11 = cx*czn - sx*sy*szn,  T12 = sx*czn + cx*sy*szn;
        float T20 = sy,      T21 = -sx*cy,              T22 = cx*cy;

        float tv0 = -p[3], tv1 = -p[4], tv2 = 1000.0f - p[5];
        float s0 = 64.0f - (T00*tv0 + T01*tv1 + T02*tv2);
        float s1 = 64.0f - (T10*tv0 + T11*tv1 + T12*tv2);
        float s2 = 64.0f - (T20*tv0 + T21*tv1 + T22*tv2);

        float qx = ((float)iu + 0.5f) * 0.001f - 0.064f;
        float qy = ((float)iv + 0.5f) * 0.001f - 0.064f;

        float d0 = T00*qx + T01*qy + T02;
        float d1 = T10*qx + T11*qy + T12;
        float d2 = T20*qx + T21*qy + T22;
        float rinv = __fdividef(1.0f, sqrtf(d0*d0 + d1*d1 + d2*d2));
        d0 *= rinv; d1 *= rinv; d2 *= rinv;

        float sd0 = (fabsf(d0) < 1e-8f) ? 1e-8f : d0;
        float sd1 = (fabsf(d1) < 1e-8f) ? 1e-8f : d1;
        float sd2 = (fabsf(d2) < 1e-8f) ? 1e-8f : d2;
        float i0 = __fdividef(1.0f, sd0);
        float i1 = __fdividef(1.0f, sd1);
        float i2 = __fdividef(1.0f, sd2);
        float a0 = (0.0f - s0) * i0, b0_ = (128.0f - s0) * i0;
        float a1 = (0.0f - s1) * i1, b1_ = (128.0f - s1) * i1;
        float a2 = (0.0f - s2) * i2, b2_ = (128.0f - s2) * i2;
        float tmin = fmaxf(fmaxf(fminf(a0,b0_), fminf(a1,b1_)), fminf(a2,b2_));
        tmin = fmaxf(tmin, 0.0f);
        float tmax = fminf(fminf(fmaxf(a0,b0_), fmaxf(a1,b1_)), fmaxf(a2,b2_));

        g_ray[ray*2 + 0] = make_float4(s0, s1, s2, tmin);
        g_ray[ray*2 + 1] = make_float4(d0, d1, d2, tmax);
    }
}

// ---------------- march ----------------
__device__ __forceinline__ float drr_lerp(
    const unsigned* __restrict__ Q,
    float px, float py, float pz)
{
    float fx = floorf(px), fy = floorf(py), fz = floorf(pz);
    float rx = px - fx, ry = py - fy, rz = pz - fz;

    int r = (int)fmaf(fx, (float)SX, fmaf(fy, (float)PZ, fz + (float)ROFF));

    unsigned w0 = __ldg(Q + r);        // corners at x
    unsigned w1 = __ldg(Q + r + SX);   // corners at x+1

    // denormal-half unpack: half = q * 2^-24 (exact)
    unsigned ua0 = __byte_perm(w0, 0, 0x4240);   // (q(y,z),   q(y+1,z))
    unsigned ua1 = __byte_perm(w0, 0, 0x4341);   // (q(y,z+1), q(y+1,z+1))
    unsigned ub0 = __byte_perm(w1, 0, 0x4240);
    unsigned ub1 = __byte_perm(w1, 0, 0x4341);
    __half2 A0 = *reinterpret_cast<__half2*>(&ua0);
    __half2 A1 = *reinterpret_cast<__half2*>(&ua1);
    __half2 B0 = *reinterpret_cast<__half2*>(&ub0);
    __half2 B1 = *reinterpret_cast<__half2*>(&ub1);

    __half2 rz2 = __float2half2_rn(rz);
    __half2 rx2 = __float2half2_rn(rx);

    __half2 LA = __hfma2(rz2, __hsub2(A1, A0), A0);   // z-lerp at x
    __half2 LB = __hfma2(rz2, __hsub2(B1, B0), B0);   // z-lerp at x+1
    __half2 M  = __hfma2(rx2, __hsub2(LB, LA), LA);   // x-lerp, channels (y, y+1)

    float2 f = __half22float2(M);
    return fmaf(ry, f.y - f.x, f.x);                  // final y-lerp in fp32
}

__device__ __forceinline__ float drr_sample_u(
    const unsigned* __restrict__ Q, float tk,
    float d0, float d1, float d2, float s0, float s1, float s2)
{
    return drr_lerp(Q, fmaf(tk, d0, s0), fmaf(tk, d1, s1), fmaf(tk, d2, s2));
}

__device__ __forceinline__ float drr_sample_m(
    const unsigned* __restrict__ Q, float tk, float tmax,
    float d0, float d1, float d2, float s0, float s1, float s2)
{
    float tc = fminf(tk, tmax);
    float s = drr_lerp(Q, fmaf(tc, d0, s0), fmaf(tc, d1, s1), fmaf(tc, d2, s2));
    return (tk < tmax) ? s : 0.0f;
}

__global__ void __launch_bounds__(WARPS_PER_BLOCK * 32, 8) drr_march_kernel(
    float* __restrict__ out)
{
    const int lane    = threadIdx.x & 31;
    const int warp_id = threadIdx.x >> 5;
    const int ray     = blockIdx.x * WARPS_PER_BLOCK + warp_id;
    const int b       = ray >> 14;

    const float4 A = __ldg(&g_ray[ray*2 + 0]);
    const float4 B = __ldg(&g_ray[ray*2 + 1]);
    const float s0 = A.x, s1 = A.y, s2 = A.z, tmin = A.w;
    const float d0 = B.x, d1 = B.y, d2 = B.z, tmax = B.w;

    const unsigned* __restrict__ Q = g_Q + (size_t)b * PBATCH;

    int nc = __float2int_ru((tmax - tmin - 0.5f) * 0.03125f);
    nc = max(0, min(nc, 8));
    const int nfull = nc - 1;

    const float t0 = tmin + ((float)lane + 0.5f);

    float acc = 0.0f;
    int j = 0;
    for (; j + 1 < nfull; j += 2) {
        float sa = drr_sample_u(Q, t0 + (float)(j * 32),      d0, d1, d2, s0, s1, s2);
        float sb = drr_sample_u(Q, t0 + (float)(j * 32 + 32), d0, d1, d2, s0, s1, s2);
        acc += sa + sb;
    }
    if (j < nfull) {
        acc += drr_sample_u(Q, t0 + (float)(j * 32), d0, d1, d2, s0, s1, s2);
        j++;
    }
    if (j < nc) {
        acc += drr_sample_m(Q, t0 + (float)(j * 32), tmax, d0, d1, d2, s0, s1, s2);
    }

    #pragma unroll
    for (int off = 16; off > 0; off >>= 1)
        acc += __shfl_xor_sync(0xFFFFFFFFu, acc, off);

    if (lane == 0)
        out[ray] = acc * (16777216.0f / 255.0f * 0.1f);   // undo 2^-24 + q-scale + STEP/10
}

extern "C" void kernel_launch(void* const* d_in, const int* in_sizes, int n_in,
                              void* d_out, int out_size)
{
    const float* vol    = (const float*)d_in[0];
    const float* params = (const float*)d_in[1];
    float* out = (float*)d_out;

    drr_prep_kernel<<<NBLK_PREP, 256>>>(vol, params);
    drr_march_kernel<<<N_RAYS / WARPS_PER_BLOCK, WARPS_PER_BLOCK * 32>>>(out);
}

// round 17
// speedup vs baseline: 1.0585x; 1.0585x over previous
#include <cuda_runtime.h>
#include <cuda_fp16.h>
#include <math.h>

#define N_RAYS (4*128*128)
#define WARPS_PER_BLOCK 8

// corner-complete u32 entries: Q(b, xp, yp, zp) bytes =
//   { q(x,y,z), q(x,y,z+1), q(x,y+1,z), q(x,y+1,z+1) },  q = round(255*v)
// xp = x+1 (x in [-1,129]), yp = y+1 (y in [-1,128]), zp = z+4 (z in [-4,131])
#define PZ 136
#define PY 130
#define PX 131
#define SX (PY*PZ)             // 17680
#define PBATCH (PX*SX)         // 2316080
#define ROFF (SX + PZ + 4)     // 17820

__device__ float4   g_ray[N_RAYS * 2];
__device__ unsigned g_Q[4 * PBATCH];       // 37 MB

// role partition of the fused prep kernel
#define NBLK_PACK   1024                   // 4*128*32*16 threads, 4 rows each
#define NBLK_Y0     32                     // 4*128*16 threads
#define NROWS_B     (4 * (3 * PY + 128))   // 2072 full zero rows
#define NSINGLE_B   (4 * 128 * 129)        // 66048 zp=132 singles
#define NBLK_BORDER ((NROWS_B + NSINGLE_B + 255) / 256)   // 267
#define NBLK_SETUP  (N_RAYS / 256)         // 256
#define NBLK_PREP   (NBLK_PACK + NBLK_Y0 + NBLK_BORDER + NBLK_SETUP)

__device__ __forceinline__ unsigned q8(float v) {
    return __float2uint_rn(v * 255.0f);
}

// load 9 consecutive z values of one volume row, quantized+packed: C0=q0..q3, C1=q4..q7, c8
__device__ __forceinline__ void load_row9(
    const float* rowz, bool valid, bool has9,
    unsigned& C0, unsigned& C1, unsigned& c8)
{
    float4 a0 = make_float4(0.f,0.f,0.f,0.f), a1 = a0;
    float nx = 0.0f;
    if (valid) {
        a0 = __ldg((const float4*)rowz);
        a1 = __ldg((const float4*)(rowz + 4));
        if (has9) nx = __ldg(rowz + 8);
    }
    C0 = q8(a0.x) | (q8(a0.y) << 8) | (q8(a0.z) << 16) | (q8(a0.w) << 24);
    C1 = q8(a1.x) | (q8(a1.y) << 8) | (q8(a1.z) << 16) | (q8(a1.w) << 24);
    c8 = q8(nx);
}

// ---------------- fused prep ----------------
__global__ void __launch_bounds__(256) drr_prep_kernel(
    const float* __restrict__ vol,
    const float* __restrict__ params)
{
    const int blk = blockIdx.x;

    if (blk < NBLK_PACK) {
        // ---- pack: rolling y over 4 rows/thread, entries yp in [1,128] ----
        const int tid = blk * 256 + threadIdx.x;   // 262144
        const int zq = tid & 15;                   // z segment of 8
        const int yg = (tid >> 4) & 31;            // y group of 4
        const int x  = (tid >> 9) & 127;
        const int b  = tid >> 16;
        const int z0 = zq * 8;
        const int y0 = yg * 4;
        const bool has9 = (zq < 15);

        const float* rbase = vol + ((size_t)(b * 128 + x) * 128 + y0) * 128 + z0;

        unsigned P0, P1, p8;
        load_row9(rbase, true, has9, P0, P1, p8);   // row y = y0

        size_t w = (size_t)b * PBATCH + (size_t)(x + 1) * SX
                 + (size_t)(y0 + 1) * PZ + (z0 + 4);

        #pragma unroll
        for (int i = 1; i <= 4; i++) {
            unsigned C0, C1, c8;
            load_row9(rbase + (size_t)i * 128, (y0 + i) < 128, has9, C0, C1, c8);

            unsigned e0 = __byte_perm(P0, C0, 0x5410);
            unsigned e1 = __byte_perm(P0, C0, 0x6521);
            unsigned e2 = __byte_perm(P0, C0, 0x7632);
            unsigned t  = __byte_perm(P0, P1, 0x0043);
            unsigned u  = __byte_perm(C0, C1, 0x0043);
            unsigned e3 = __byte_perm(t, u, 0x5410);
            unsigned e4 = __byte_perm(P1, C1, 0x5410);
            unsigned e5 = __byte_perm(P1, C1, 0x6521);
            unsigned e6 = __byte_perm(P1, C1, 0x7632);
            unsigned t2 = __byte_perm(P1, p8, 0x0043);
            unsigned u2 = __byte_perm(C1, c8, 0x0043);
            unsigned e7 = __byte_perm(t2, u2, 0x5410);

            *reinterpret_cast<uint4*>(&g_Q[w])     = make_uint4(e0, e1, e2, e3);
            *reinterpret_cast<uint4*>(&g_Q[w + 4]) = make_uint4(e4, e5, e6, e7);

            if (zq == 0)   // entry z = -1 (zp = 3): {0, q(y,0), 0, q(y+1,0)}
                g_Q[w - 1] = ((P0 & 0xFFu) << 8) | ((C0 & 0xFFu) << 24);

            P0 = C0; P1 = C1; p8 = c8;
            w += PZ;
        }
        return;
    }

    if (blk < NBLK_PACK + NBLK_Y0) {
        // ---- yp = 0 plane (y = -1): bytes {0, 0, q(0,z), q(0,z+1)} ----
        const int tid = (blk - NBLK_PACK) * 256 + threadIdx.x;   // 8192
        const int zq = tid & 15;
        const int x  = (tid >> 4) & 127;
        const int b  = tid >> 11;
        const int z0 = zq * 8;
        const bool has9 = (zq < 15);

        const float* rbase = vol + ((size_t)(b * 128 + x) * 128) * 128 + z0;   // row y=0
        unsigned C0, C1, c8;
        load_row9(rbase, true, has9, C0, C1, c8);

        unsigned e0 = __byte_perm(C0, 0, 0x1044);
        unsigned e1 = __byte_perm(C0, 0, 0x2144);
        unsigned e2 = __byte_perm(C0, 0, 0x3244);
        unsigned u  = __byte_perm(C0, C1, 0x0043);
        unsigned e3 = __byte_perm(u, 0, 0x1044);
        unsigned e4 = __byte_perm(C1, 0, 0x1044);
        unsigned e5 = __byte_perm(C1, 0, 0x2144);
        unsigned e6 = __byte_perm(C1, 0, 0x3244);
        unsigned u2 = __byte_perm(C1, c8, 0x0043);
        unsigned e7 = __byte_perm(u2, 0, 0x1044);

        size_t w = (size_t)b * PBATCH + (size_t)(x + 1) * SX + (z0 + 4);
        *reinterpret_cast<uint4*>(&g_Q[w])     = make_uint4(e0, e1, e2, e3);
        *reinterpret_cast<uint4*>(&g_Q[w + 4]) = make_uint4(e4, e5, e6, e7);

        if (zq == 0)   // entry (y=-1, z=-1): {0,0,0,q(0,0)}
            g_Q[w - 1] = (C0 & 0xFFu) << 24;
        return;
    }

    if (blk < NBLK_PACK + NBLK_Y0 + NBLK_BORDER) {
        // ---- borders: full zero rows + zp=132 singles ----
        const int t = (blk - NBLK_PACK - NBLK_Y0) * 256 + threadIdx.x;
        if (t < NROWS_B) {
            const int b = t / (3 * PY + 128);
            int r = t % (3 * PY + 128);
            int xp, yp;
            if (r < 3 * PY) {
                const int pl = r / PY;
                xp = (pl == 0) ? 0 : (pl == 1 ? 129 : 130);
                yp = r % PY;
            } else {
                xp = 1 + (r - 3 * PY);
                yp = 129;
            }
            size_t base = (size_t)b * PBATCH + (size_t)xp * SX + (size_t)yp * PZ;
            uint4 z4 = make_uint4(0u, 0u, 0u, 0u);
            #pragma unroll
            for (int i = 0; i < PZ / 4; i++)
                *reinterpret_cast<uint4*>(&g_Q[base + i * 4]) = z4;
            return;
        }
        const int s = t - NROWS_B;
        if (s >= NSINGLE_B) return;
        const int yp = s % 129;
        const int xq = (s / 129) & 127;
        const int b  = s / (129 * 128);
        g_Q[(size_t)b * PBATCH + (size_t)(xq + 1) * SX + (size_t)yp * PZ + 132] = 0u;
        return;
    }

    // ---- setup: per-ray geometry ----
    {
        const int ray = (blk - NBLK_PACK - NBLK_Y0 - NBLK_BORDER) * 256 + threadIdx.x;
        const int iv = ray & 127;
        const int iu = (ray >> 7) & 127;
        const int b  = ray >> 14;

        const float* p = params + b * 6;
        float sx, cx, sy, cy, szn, czn;
        __sincosf(p[0], &sx, &cx);
        __sincosf(p[1], &sy, &cy);
        __sincosf(p[2], &szn, &czn);

        float T00 = cy*czn,  T01 = cx*szn + sx*sy*czn,  T02 = sx*szn - cx*sy*czn;
        float T10 = -cy*szn, T11 = cx*czn - sx*sy*szn,  T12 = sx*czn + cx*sy*szn;
        float T20 = sy,      T21 = -sx*cy,              T22 = cx*cy;

        float tv0 = -p[3], tv1 = -p[4], tv2 = 1000.0f - p[5];
        float s0 = 64.0f - (T00*tv0 + T01*tv1 + T02*tv2);
        float s1 = 64.0f - (T10*tv0 + T11*tv1 + T12*tv2);
        float s2 = 64.0f - (T20*tv0 + T21*tv1 + T22*tv2);

        float qx = ((float)iu + 0.5f) * 0.001f - 0.064f;
        float qy = ((float)iv + 0.5f) * 0.001f - 0.064f;

        float d0 = T00*qx + T01*qy + T02;
        float d1 = T10*qx + T11*qy + T12;
        float d2 = T20*qx + T21*qy + T22;
        float rinv = __fdividef(1.0f, sqrtf(d0*d0 + d1*d1 + d2*d2));
        d0 *= rinv; d1 *= rinv; d2 *= rinv;

        float sd0 = (fabsf(d0) < 1e-8f) ? 1e-8f : d0;
        float sd1 = (fabsf(d1) < 1e-8f) ? 1e-8f : d1;
        float sd2 = (fabsf(d2) < 1e-8f) ? 1e-8f : d2;
        float i0 = __fdividef(1.0f, sd0);
        float i1 = __fdividef(1.0f, sd1);
        float i2 = __fdividef(1.0f, sd2);
        float a0 = (0.0f - s0) * i0, b0_ = (128.0f - s0) * i0;
        float a1 = (0.0f - s1) * i1, b1_ = (128.0f - s1) * i1;
        float a2 = (0.0f - s2) * i2, b2_ = (128.0f - s2) * i2;
        float tmin = fmaxf(fmaxf(fminf(a0,b0_), fminf(a1,b1_)), fminf(a2,b2_));
        tmin = fmaxf(tmin, 0.0f);
        float tmax = fminf(fminf(fmaxf(a0,b0_), fmaxf(a1,b1_)), fmaxf(a2,b2_));

        g_ray[ray*2 + 0] = make_float4(s0, s1, s2, tmin);
        g_ray[ray*2 + 1] = make_float4(d0, d1, d2, tmax);
    }
}

// ---------------- march (round-16 body, unchanged) ----------------
__device__ __forceinline__ float drr_lerp(
    const unsigned* __restrict__ Q,
    float px, float py, float pz)
{
    float fx = floorf(px), fy = floorf(py), fz = floorf(pz);
    float rx = px - fx, ry = py - fy, rz = pz - fz;

    int r = (int)fmaf(fx, (float)SX, fmaf(fy, (float)PZ, fz + (float)ROFF));

    unsigned w0 = __ldg(Q + r);        // corners at x
    unsigned w1 = __ldg(Q + r + SX);   // corners at x+1

    // denormal-half unpack: half = q * 2^-24 (exact)
    unsigned ua0 = __byte_perm(w0, 0, 0x4240);   // (q(y,z),   q(y+1,z))
    unsigned ua1 = __byte_perm(w0, 0, 0x4341);   // (q(y,z+1), q(y+1,z+1))
    unsigned ub0 = __byte_perm(w1, 0, 0x4240);
    unsigned ub1 = __byte_perm(w1, 0, 0x4341);
    __half2 A0 = *reinterpret_cast<__half2*>(&ua0);
    __half2 A1 = *reinterpret_cast<__half2*>(&ua1);
    __half2 B0 = *reinterpret_cast<__half2*>(&ub0);
    __half2 B1 = *reinterpret_cast<__half2*>(&ub1);

    __half2 rz2 = __float2half2_rn(rz);
    __half2 rx2 = __float2half2_rn(rx);

    __half2 LA = __hfma2(rz2, __hsub2(A1, A0), A0);   // z-lerp at x
    __half2 LB = __hfma2(rz2, __hsub2(B1, B0), B0);   // z-lerp at x+1
    __half2 M  = __hfma2(rx2, __hsub2(LB, LA), LA);   // x-lerp, channels (y, y+1)

    float2 f = __half22float2(M);
    return fmaf(ry, f.y - f.x, f.x);                  // final y-lerp in fp32
}

__device__ __forceinline__ float drr_sample_u(
    const unsigned* __restrict__ Q, float tk,
    float d0, float d1, float d2, float s0, float s1, float s2)
{
    return drr_lerp(Q, fmaf(tk, d0, s0), fmaf(tk, d1, s1), fmaf(tk, d2, s2));
}

__device__ __forceinline__ float drr_sample_m(
    const unsigned* __restrict__ Q, float tk, float tmax,
    float d0, float d1, float d2, float s0, float s1, float s2)
{
    float tc = fminf(tk, tmax);
    float s = drr_lerp(Q, fmaf(tc, d0, s0), fmaf(tc, d1, s1), fmaf(tc, d2, s2));
    return (tk < tmax) ? s : 0.0f;
}

__global__ void __launch_bounds__(WARPS_PER_BLOCK * 32, 8) drr_march_kernel(
    float* __restrict__ out)
{
    const int lane    = threadIdx.x & 31;
    const int warp_id = threadIdx.x >> 5;
    const int ray     = blockIdx.x * WARPS_PER_BLOCK + warp_id;
    const int b       = ray >> 14;

    const float4 A = __ldg(&g_ray[ray*2 + 0]);
    const float4 B = __ldg(&g_ray[ray*2 + 1]);
    const float s0 = A.x, s1 = A.y, s2 = A.z, tmin = A.w;
    const float d0 = B.x, d1 = B.y, d2 = B.z, tmax = B.w;

    const unsigned* __restrict__ Q = g_Q + (size_t)b * PBATCH;

    int nc = __float2int_ru((tmax - tmin - 0.5f) * 0.03125f);
    nc = max(0, min(nc, 8));
    const int nfull = nc - 1;

    const float t0 = tmin + ((float)lane + 0.5f);

    float acc = 0.0f;
    int j = 0;
    for (; j + 1 < nfull; j += 2) {
        float sa = drr_sample_u(Q, t0 + (float)(j * 32),      d0, d1, d2, s0, s1, s2);
        float sb = drr_sample_u(Q, t0 + (float)(j * 32 + 32), d0, d1, d2, s0, s1, s2);
        acc += sa + sb;
    }
    if (j < nfull) {
        acc += drr_sample_u(Q, t0 + (float)(j * 32), d0, d1, d2, s0, s1, s2);
        j++;
    }
    if (j < nc) {
        acc += drr_sample_m(Q, t0 + (float)(j * 32), tmax, d0, d1, d2, s0, s1, s2);
    }

    #pragma unroll
    for (int off = 16; off > 0; off >>= 1)
        acc += __shfl_xor_sync(0xFFFFFFFFu, acc, off);

    if (lane == 0)
        out[ray] = acc * (16777216.0f / 255.0f * 0.1f);   // undo 2^-24 + q-scale + STEP/10
}

extern "C" void kernel_launch(void* const* d_in, const int* in_sizes, int n_in,
                              void* d_out, int out_size)
{
    const float* vol    = (const float*)d_in[0];
    const float* params = (const float*)d_in[1];
    float* out = (float*)d_out;

    drr_prep_kernel<<<NBLK_PREP, 256>>>(vol, params);
    drr_march_kernel<<<N_RAYS / WARPS_PER_BLOCK, WARPS_PER_BLOCK * 32>>>(out);
}